// round 7
// baseline (speedup 1.0000x reference)
#include <cuda_runtime.h>
#include <cstdint>

#define KTOP 2048
#define DD 128
#define HBINS 8192            // 13-bit key prefix
#define HSHIFT 19             // 32 - 13
#define CAND_MAX 4608
#define TPB 512
#define NB_CAP 1024
#define CHUNK 512             // rows per phase-1 ticket

// ---- static scratch (no allocations allowed) ----
__device__ unsigned int g_hist[HBINS];
__device__ float g_y[500224];
__device__ unsigned int g_cnt;
__device__ unsigned int g_tick;
__device__ unsigned int g_done;
__device__ __align__(16) unsigned long long g_cand[CAND_MAX];
__device__ unsigned int g_bar_count;
__device__ volatile unsigned int g_bar_gen;

// monotonic unsigned key for f32 ordering
__device__ __forceinline__ unsigned int fkey(float f) {
    unsigned int u = __float_as_uint(f);
    return (u & 0x80000000u) ? ~u : (u | 0x80000000u);
}
__device__ __forceinline__ float dot4(float4 a, float4 b) {
    return a.x * b.x + a.y * b.y + a.z * b.z + a.w * b.w;
}

// software grid barrier (all blocks co-resident by construction)
__device__ __forceinline__ void grid_bar(int nb) {
    __threadfence();
    __syncthreads();
    if (threadIdx.x == 0) {
        unsigned int gen = g_bar_gen;
        if (atomicAdd(&g_bar_count, 1u) == (unsigned int)(nb - 1)) {
            g_bar_count = 0u;
            __threadfence();
            g_bar_gen = gen + 1u;
        } else {
            while (g_bar_gen == gen) { __nanosleep(64); }
        }
    }
    __syncthreads();
}

__device__ __forceinline__ void try_push(float y, int i, unsigned int tb) {
    unsigned int key = fkey(y);
    if ((key >> HSHIFT) >= tb) {
        unsigned int pos = atomicAdd(&g_cnt, 1u);
        if (pos < CAND_MAX) {
            // value-descending major, index-ascending minor
            g_cand[pos] = ((unsigned long long)key << 32) |
                          (unsigned long long)(~(unsigned int)i);
        }
    }
}

__global__ void __launch_bounds__(TPB, 2)
mega(const float* __restrict__ x, const float* __restrict__ p,
     float* __restrict__ out, int n, int nb)
{
    const int tid = threadIdx.x;
    const int lane = tid & 31;
    const int l8 = lane & 7;
    const int grp = lane >> 3;
    const int gtid = blockIdx.x * TPB + tid;
    const int gthreads = nb * TPB;

    // union: phase-1 smem histogram (8192 u32 = 32 KB) / phase-4 keys (4608 u64)
    __shared__ __align__(16) unsigned char sbuf[36864];
    unsigned int* shist = reinterpret_cast<unsigned int*>(sbuf);
    unsigned long long* sk = reinterpret_cast<unsigned long long*>(sbuf);
    __shared__ unsigned int ss[512];
    __shared__ unsigned int swt[16], saf[16];
    __shared__ unsigned int s_tbin;
    __shared__ int s_base;
    __shared__ int s_rk[64];
    __shared__ int s_ridx[64];
    __shared__ float s_rt[64];

    // ---- phase 0: norm (per-warp, registers only) ----
    const float4* __restrict__ p4 = reinterpret_cast<const float4*>(p);
    float4 q0 = p4[l8], q1 = p4[l8 + 8], q2 = p4[l8 + 16], q3 = p4[l8 + 24];
    float s2 = (dot4(q0, q0) + dot4(q1, q1)) + (dot4(q2, q2) + dot4(q3, q3));
    s2 += __shfl_xor_sync(0xffffffffu, s2, 1);
    s2 += __shfl_xor_sync(0xffffffffu, s2, 2);
    s2 += __shfl_xor_sync(0xffffffffu, s2, 4);
    const float inv = 1.0f / sqrtf(s2);

    // ---- phase 1: coalesced dot with dynamic 512-row tickets ----
    for (int i = tid; i < HBINS; i += TPB) shist[i] = 0u;
    __syncthreads();

    const float4* __restrict__ x4 = reinterpret_cast<const float4*>(x);
    const int n8 = n & ~7;
    const int wib = tid >> 5;           // warp in block (16)

    for (;;) {
        if (tid == 0) s_base = (int)(atomicAdd(&g_tick, 1u) * CHUNK);
        __syncthreads();
        int base = s_base;
        __syncthreads();
        if (base >= n8) break;
        int end = base + CHUNK; if (end > n8) end = n8;
        for (int r0 = base + wib * 8; r0 < end; r0 += 16 * 8) {
            int rA = r0 + grp;
            int rB = rA + 4;
            const float4* xa = x4 + (size_t)rA * 32 + l8;
            const float4* xb = x4 + (size_t)rB * 32 + l8;
            float4 a0 = __ldcs(xa + 0), a1 = __ldcs(xa + 8),
                   a2 = __ldcs(xa + 16), a3 = __ldcs(xa + 24);
            float4 b0 = __ldcs(xb + 0), b1 = __ldcs(xb + 8),
                   b2 = __ldcs(xb + 16), b3 = __ldcs(xb + 24);
            float sA = (dot4(a0, q0) + dot4(a1, q1)) + (dot4(a2, q2) + dot4(a3, q3));
            float sB = (dot4(b0, q0) + dot4(b1, q1)) + (dot4(b2, q2) + dot4(b3, q3));
            sA += __shfl_xor_sync(0xffffffffu, sA, 1);
            sB += __shfl_xor_sync(0xffffffffu, sB, 1);
            sA += __shfl_xor_sync(0xffffffffu, sA, 2);
            sB += __shfl_xor_sync(0xffffffffu, sB, 2);
            sA += __shfl_xor_sync(0xffffffffu, sA, 4);
            sB += __shfl_xor_sync(0xffffffffu, sB, 4);
            if (l8 == 0) {
                float yA = sA * inv;
                float yB = sB * inv;
                g_y[rA] = yA;
                g_y[rB] = yB;
                atomicAdd(&shist[fkey(yA) >> HSHIFT], 1u);
                atomicAdd(&shist[fkey(yB) >> HSHIFT], 1u);
            }
        }
    }
    // tail rows [n8, n): block 0 / warp 0, full-width dot
    if (blockIdx.x == 0 && tid < 32 && n8 < n) {
        float4 pl = p4[lane];
        for (int r = n8; r < n; r++) {
            float4 v = x4[(size_t)r * 32 + lane];
            float s = dot4(v, pl);
            #pragma unroll
            for (int o = 16; o; o >>= 1) s += __shfl_xor_sync(0xffffffffu, s, o);
            if (lane == 0) {
                float y = s * inv;
                g_y[r] = y;
                atomicAdd(&shist[fkey(y) >> HSHIFT], 1u);
            }
        }
    }
    __syncthreads();
    for (int i = tid; i < HBINS; i += TPB) {
        unsigned int v = shist[i];
        if (v) atomicAdd(&g_hist[i], v);
    }
    grid_bar(nb);
    if (gtid == 0) g_tick = 0u;         // safe: no reader until next replay

    // ---- phase 2 (every block, redundant): find threshold bin ----
    {
        const uint4* h4 = reinterpret_cast<const uint4*>(g_hist) + tid * 4;
        uint4 a = h4[0], b = h4[1], c = h4[2], d = h4[3];
        unsigned int part = a.x + a.y + a.z + a.w + b.x + b.y + b.z + b.w
                          + c.x + c.y + c.z + c.w + d.x + d.y + d.z + d.w;
        // within-warp inclusive suffix sum
        unsigned int s = part;
        #pragma unroll
        for (int off = 1; off < 32; off <<= 1) {
            unsigned int v = __shfl_down_sync(0xffffffffu, s, off);
            if (lane + off < 32) s += v;
        }
        if (lane == 0) swt[wib] = s;
        __syncthreads();
        if (tid < 16) {
            unsigned int acc = 0;
            for (int i = tid + 1; i < 16; i++) acc += swt[i];
            saf[tid] = acc;
        }
        __syncthreads();
        unsigned int incl = s + saf[wib];
        unsigned int nxt = incl - part;
        if (incl >= KTOP && nxt < KTOP) {
            unsigned int acc = nxt;
            for (int bi = tid * 16 + 15; bi >= tid * 16; bi--) {
                acc += g_hist[bi];
                if (acc >= KTOP) { s_tbin = (unsigned int)bi; break; }
            }
        }
        __syncthreads();
    }

    // ---- phase 3: compact candidates (whole grid, one float4/thread) ----
    {
        unsigned int tb = s_tbin;
        int n4 = n >> 2;
        const float4* __restrict__ y4 = reinterpret_cast<const float4*>(g_y);
        for (int i = gtid; i < n4; i += gthreads) {
            float4 v = y4[i];
            try_push(v.x, i * 4 + 0, tb);
            try_push(v.y, i * 4 + 1, tb);
            try_push(v.z, i * 4 + 2, tb);
            try_push(v.w, i * 4 + 3, tb);
        }
        if (gtid == 0) {
            for (int j = n & ~3; j < n; j++) try_push(g_y[j], j, tb);
        }
    }
    grid_bar(nb);

    // ---- phase 4 (fused rank + gather + write): 64 candidates/block ----
    {
        int C = (int)min(g_cnt, (unsigned int)CAND_MAX);
        int nactive = (C + 63) >> 6;
        if (blockIdx.x < nactive) {
            for (int i = tid; i < C; i += TPB) sk[i] = g_cand[i];
            __syncthreads();
            // all threads of this block have read g_cnt; handshake the reset
            if (tid == 0) {
                if (atomicAdd(&g_done, 1u) + 1u == (unsigned int)nactive) {
                    g_cnt = 0u;
                    g_done = 0u;
                }
            }
            int j = tid & 63;
            int seg = tid >> 6;        // 8 segments
            int jg = blockIdx.x * 64 + j;
            unsigned long long pk = (jg < C) ? sk[jg] : ~0ull;
            int segsz = (C + 7) >> 3;
            int lo = seg * segsz;
            int hi = lo + segsz; if (hi > C) hi = C;
            int part = 0;
            int i = lo;
            for (; i + 4 <= hi; i += 4) {
                part += (sk[i + 0] > pk);
                part += (sk[i + 1] > pk);
                part += (sk[i + 2] > pk);
                part += (sk[i + 3] > pk);
            }
            for (; i < hi; i++) part += (sk[i] > pk);
            ss[tid] = (unsigned int)part;
            __syncthreads();
            if (tid < 64) {
                int rk = -1, idx = 0;
                float tv = 0.f;
                if (jg < C) {
                    int rank = (int)(ss[tid] + ss[tid + 64] + ss[tid + 128] +
                                     ss[tid + 192] + ss[tid + 256] + ss[tid + 320] +
                                     ss[tid + 384] + ss[tid + 448]);
                    if (rank < KTOP) {
                        unsigned int key = (unsigned int)(pk >> 32);
                        unsigned int u = (key & 0x80000000u) ? (key ^ 0x80000000u) : ~key;
                        rk = rank;
                        idx = (int)(~(unsigned int)(pk & 0xFFFFFFFFull));
                        tv = tanhf(__uint_as_float(u));
                    }
                }
                s_rk[tid] = rk;
                s_ridx[tid] = idx;
                s_rt[tid] = tv;
            }
            __syncthreads();
            // gather + write: 8 threads per candidate, 4 float4 each
            {
                int c = tid >> 3;
                int sg = tid & 7;
                int rk = s_rk[c];
                if (rk >= 0) {
                    int idx = s_ridx[c];
                    float tv = s_rt[c];
                    const float4* xr = x4 + (size_t)idx * 32 + sg;
                    float4* orow = reinterpret_cast<float4*>(out) + (size_t)rk * 32 + sg;
                    float4 v0 = xr[0], v1 = xr[8], v2 = xr[16], v3 = xr[24];
                    orow[0]  = make_float4(v0.x * tv, v0.y * tv, v0.z * tv, v0.w * tv);
                    orow[8]  = make_float4(v1.x * tv, v1.y * tv, v1.z * tv, v1.w * tv);
                    orow[16] = make_float4(v2.x * tv, v2.y * tv, v2.z * tv, v2.w * tv);
                    orow[24] = make_float4(v3.x * tv, v3.y * tv, v3.z * tv, v3.w * tv);
                }
            }
        }
    }

    // ---- replay-state reset (no barrier needed: kernel end syncs) ----
    for (int i = gtid; i < HBINS; i += gthreads) g_hist[i] = 0u;
}

extern "C" void kernel_launch(void* const* d_in, const int* in_sizes, int n_in,
                              void* d_out, int out_size) {
    const float* x = (const float*)d_in[0];
    const float* p = (const float*)d_in[1];
    int n = in_sizes[0] / DD;

    int dev = 0;
    cudaGetDevice(&dev);
    int sm = 0;
    cudaDeviceGetAttribute(&sm, cudaDevAttrMultiProcessorCount, dev);
    int bpsm = 0;
    cudaOccupancyMaxActiveBlocksPerMultiprocessor(&bpsm, mega, TPB, 0);
    if (bpsm < 1) bpsm = 1;
    int nb = sm * bpsm;
    if (nb > NB_CAP) nb = NB_CAP;

    mega<<<nb, TPB>>>(x, p, (float*)d_out, n, nb);
}